// round 15
// baseline (speedup 1.0000x reference)
#include <cuda_runtime.h>
#include <cuda_bf16.h>
#include <cstdint>
#include <math.h>

#define NTD 16
#define NRD 2048

// ---------------- scratch (plain row-major, hi/lo bf16 planes) ----------------
__device__ __nv_bfloat16 g_A1[(size_t)16*2*4096*256];   // 64MB  [t][p][m][k]
__device__ __nv_bfloat16 g_B1[(size_t)16*2*1024*256];   // 16MB  [t][p][n][k]
__device__ __nv_bfloat16 g_A2[(size_t)16*2*256*4096];   // 64MB
__device__ __nv_bfloat16 g_B2[(size_t)16*2*1024*4096];  // 256MB
__device__ float  g_C1[(size_t)16*4096*1024];           // 256MB
__device__ float  g_C2[(size_t)16*256*1024];            // 16MB
__device__ float2 g_Ey[(size_t)16*2048*128];            // [t][k][y]
__device__ float2 g_EyT[(size_t)16*128*2048];           // [t][y][k]
__device__ float2 g_g[(size_t)16*8*2048];               // weighted kdat

// write hi/lo split
__device__ __forceinline__ void wr2(__nv_bfloat16* p, size_t ps, float v) {
    __nv_bfloat16 h = __float2bfloat16(v);
    p[0]  = h;
    p[ps] = __float2bfloat16(v - __bfloat162float(h));
}

// ---------------- generators ----------------
__global__ void k_expoA(const float* __restrict__ kt) {
    int idx = blockIdx.x * blockDim.x + threadIdx.x;
    if (idx >= NTD * NRD * 128) return;
    int x = idx & 127, k = (idx >> 7) & 2047, t = idx >> 18;
    float kx = kt[k * NTD + t], ky = kt[(NRD + k) * NTD + t];
    float p = (float)(x - 64);
    float s1, c1, s2, c2;
    sincosf(kx * p, &s1, &c1);
    sincosf(ky * p, &s2, &c2);
    g_Ey[((size_t)t * 2048 + k) * 128 + x] = make_float2(c2, -s2);
    const size_t PS = (size_t)4096 * 256;
    __nv_bfloat16* At = g_A1 + (size_t)t * 2 * PS;
    wr2(At + (size_t)k * 256 + x,              PS,  c1);
    wr2(At + (size_t)k * 256 + 128 + x,        PS,  s1);
    wr2(At + (size_t)(2048 + k) * 256 + x,     PS, -s1);
    wr2(At + (size_t)(2048 + k) * 256 + 128 + x, PS, c1);
}
__global__ void k_expoB(const float* __restrict__ kt) {
    int idx = blockIdx.x * blockDim.x + threadIdx.x;
    if (idx >= NTD * 128 * NRD) return;
    int k = idx & 2047, x = (idx >> 11) & 127, t = idx >> 18;
    float kx = kt[k * NTD + t], ky = kt[(NRD + k) * NTD + t];
    float p = (float)(x - 64);
    float s1, c1, s2, c2;
    sincosf(kx * p, &s1, &c1);
    sincosf(ky * p, &s2, &c2);
    g_EyT[((size_t)t * 128 + x) * 2048 + k] = make_float2(c2, -s2);
    const size_t PS = (size_t)256 * 4096;
    __nv_bfloat16* At = g_A2 + (size_t)t * 2 * PS;
    wr2(At + (size_t)x * 4096 + k,               PS,  c1);
    wr2(At + (size_t)x * 4096 + 2048 + k,        PS, -s1);
    wr2(At + (size_t)(128 + x) * 4096 + k,       PS,  s1);
    wr2(At + (size_t)(128 + x) * 4096 + 2048 + k, PS, c1);
}
__global__ void k_src(const float* __restrict__ xin, const float* __restrict__ csmap) {
    int idx = blockIdx.x * blockDim.x + threadIdx.x;
    if (idx >= NTD * 8 * 128 * 128) return;
    int x = idx & 127, y = (idx >> 7) & 127, c = (idx >> 14) & 7, t = idx >> 17;
    float ir = xin[((0 + x) * 128 + y) * 16 + t];
    float ii = xin[((128 + x) * 128 + y) * 16 + t];
    float sr = csmap[((c * 2 + 0) * 128 + x) * 128 + y];
    float si = csmap[((c * 2 + 1) * 128 + x) * 128 + y];
    float vr = sr * ir - si * ii, vi = sr * ii + si * ir;
    const size_t PS = (size_t)1024 * 256;
    __nv_bfloat16* Bt = g_B1 + (size_t)t * 2 * PS;
    wr2(Bt + (size_t)(c * 128 + y) * 256 + x,       PS, vr);
    wr2(Bt + (size_t)(c * 128 + y) * 256 + 128 + x, PS, vi);
}
// g[c,k] = (sum_y Ey*t1) * d / 16384
__global__ void k_kdat(const float* __restrict__ dcomp) {
    int gt = blockIdx.x * blockDim.x + threadIdx.x;
    int w = gt >> 5, lane = gt & 31;
    if (w >= NTD * 8 * 2048) return;
    int k = w & 2047, c = (w >> 11) & 7, t = w >> 14;
    size_t ro = ((size_t)t * 4096 + k) * 1024 + c * 128;
    size_t io = ((size_t)t * 4096 + 2048 + k) * 1024 + c * 128;
    size_t eo = ((size_t)t * 2048 + k) * 128;
    float ar = 0.f, ai = 0.f;
    #pragma unroll
    for (int i = 0; i < 4; i++) {
        int y = lane + 32 * i;
        float re = g_C1[ro + y], im = g_C1[io + y];
        float2 e = g_Ey[eo + y];
        ar += e.x * re - e.y * im;
        ai += e.x * im + e.y * re;
    }
    #pragma unroll
    for (int o = 16; o; o >>= 1) {
        ar += __shfl_xor_sync(0xffffffffu, ar, o);
        ai += __shfl_xor_sync(0xffffffffu, ai, o);
    }
    if (lane == 0) {
        float d = dcomp[k * NTD + t] * (1.0f / 16384.0f);
        g_g[((size_t)(t * 8 + c)) * 2048 + k] = make_float2(ar * d, ai * d);
    }
}
// B2 = t2 = conj(Ey) * g  (rank-1 regen)
__global__ void k_B2(int) {
    int idx = blockIdx.x * blockDim.x + threadIdx.x;
    if (idx >= NTD * 8 * 128 * 2048) return;
    int k = idx & 2047, y = (idx >> 11) & 127, c = (idx >> 18) & 7, t = idx >> 21;
    float2 e = g_EyT[((size_t)t * 128 + y) * 2048 + k];
    float2 g = g_g[((size_t)(t * 8 + c)) * 2048 + k];
    float tr = e.x * g.x + e.y * g.y;
    float ti = e.x * g.y - e.y * g.x;
    const size_t PS = (size_t)1024 * 4096;
    __nv_bfloat16* Bt = g_B2 + (size_t)t * 2 * PS;
    wr2(Bt + (size_t)(c * 128 + y) * 4096 + k,        PS, tr);
    wr2(Bt + (size_t)(c * 128 + y) * 4096 + 2048 + k, PS, ti);
}
__global__ void k_combine(const float* __restrict__ csmap, float* __restrict__ out) {
    int idx = blockIdx.x * blockDim.x + threadIdx.x;
    if (idx >= NTD * 128 * 128) return;
    int y = idx & 127, x = (idx >> 7) & 127, t = idx >> 14;
    float orr = 0.f, oii = 0.f;
    #pragma unroll
    for (int c = 0; c < 8; c++) {
        float sr = csmap[((c * 2 + 0) * 128 + x) * 128 + y];
        float si = csmap[((c * 2 + 1) * 128 + x) * 128 + y];
        float vr = g_C2[((size_t)t * 256 + x) * 1024 + c * 128 + y];
        float vi = g_C2[((size_t)t * 256 + 128 + x) * 1024 + c * 128 + y];
        orr += sr * vr + si * vi;
        oii += sr * vi - si * vr;
    }
    out[((0 + x) * 128 + y) * 16 + t] = orr;
    out[((128 + x) * 128 + y) * 16 + t] = oii;
}

// ---------------- HMMA GEMM (mma.sync m16n8k16 bf16, 3-product split) ----------------
__device__ __forceinline__ void mma16816(float* d, const uint32_t* a, const uint32_t* b) {
    asm volatile(
        "mma.sync.aligned.m16n8k16.row.col.f32.bf16.bf16.f32 "
        "{%0,%1,%2,%3}, {%4,%5,%6,%7}, {%8,%9}, {%0,%1,%2,%3};"
        : "+f"(d[0]), "+f"(d[1]), "+f"(d[2]), "+f"(d[3])
        : "r"(a[0]), "r"(a[1]), "r"(a[2]), "r"(a[3]), "r"(b[0]), "r"(b[1]));
}

// C[t][MGLB][1024] = A[t][p][MGLB][KGLB] x B[t][p][1024][KGLB]^T with hi/lo split.
// CTA tile CTAM x 128, BK=32, 8 warps (2 x 4), warp tile (CTAM/2) x 32.
template<int CTAM, int KGLB, int MGLB>
__global__ __launch_bounds__(256)
void k_hmma(const __nv_bfloat16* __restrict__ Ag, const __nv_bfloat16* __restrict__ Bg,
            float* __restrict__ Cg) {
    constexpr int WM = CTAM / 2;          // warp m tile
    constexpr int MF = WM / 16;           // m-frags per warp
    constexpr int KC = KGLB / 32;         // k stages
    constexpr int AP = CTAM * 80;         // A plane bytes in smem (padded rows)
    constexpr int BP = 128 * 80;
    constexpr int SB = 2 * AP + 2 * BP;   // per-stage bytes
    constexpr int NA = CTAM * 8;          // A uint4 chunks (2 planes)
    constexpr int NCH = (NA + 1024) / 256;

    extern __shared__ char sm[];
    const int tid = threadIdx.x, lane = tid & 31, wid = tid >> 5;
    const int wm = wid & 1, wn = wid >> 1;
    const int t = blockIdx.z, m0 = blockIdx.y * CTAM, n0 = blockIdx.x * 128;

    float acc[MF][4][4];
    #pragma unroll
    for (int i = 0; i < MF; i++)
        #pragma unroll
        for (int j = 0; j < 4; j++)
            #pragma unroll
            for (int q = 0; q < 4; q++) acc[i][j][q] = 0.f;

    auto gsrc = [&](int i, int k0) -> const uint4* {
        if (i < NA) {
            int p = i / (CTAM * 4), r = (i >> 2) % CTAM, c = i & 3;
            return (const uint4*)(Ag + ((size_t)(t * 2 + p) * MGLB + m0 + r) * KGLB + k0 + c * 8);
        } else {
            int j = i - NA;
            int p = j >> 9, r = (j >> 2) & 127, c = j & 3;
            return (const uint4*)(Bg + ((size_t)(t * 2 + p) * 1024 + n0 + r) * KGLB + k0 + c * 8);
        }
    };
    auto sdst = [&](int i, int buf) -> uint4* {
        if (i < NA) {
            int p = i / (CTAM * 4), r = (i >> 2) % CTAM, c = i & 3;
            return (uint4*)(sm + buf * SB + p * AP + r * 80 + c * 16);
        } else {
            int j = i - NA;
            int p = j >> 9, r = (j >> 2) & 127, c = j & 3;
            return (uint4*)(sm + buf * SB + 2 * AP + p * BP + r * 80 + c * 16);
        }
    };

    // prologue: stage 0
    {
        uint4 rg[NCH];
        #pragma unroll
        for (int u = 0; u < NCH; u++) rg[u] = *gsrc(tid + u * 256, 0);
        #pragma unroll
        for (int u = 0; u < NCH; u++) *sdst(tid + u * 256, 0) = rg[u];
    }
    __syncthreads();

    for (int s = 0; s < KC; s++) {
        const int buf = s & 1;
        uint4 rg[NCH];
        if (s + 1 < KC) {
            #pragma unroll
            for (int u = 0; u < NCH; u++) rg[u] = *gsrc(tid + u * 256, (s + 1) * 32);
        }
        // compute on buf
        const char* base = sm + buf * SB;
        const int r = lane >> 2, q = lane & 3;
        #pragma unroll
        for (int ks = 0; ks < 2; ks++) {
            const int koff = ks * 32 + q * 4;
            uint32_t ah[MF][4], al[MF][4], bh[4][2], bl[4][2];
            #pragma unroll
            for (int i = 0; i < MF; i++) {
                int ro = (wm * WM + i * 16 + r) * 80 + koff;
                ah[i][0] = *(const uint32_t*)(base + ro);
                ah[i][1] = *(const uint32_t*)(base + ro + 640);
                ah[i][2] = *(const uint32_t*)(base + ro + 16);
                ah[i][3] = *(const uint32_t*)(base + ro + 656);
                al[i][0] = *(const uint32_t*)(base + AP + ro);
                al[i][1] = *(const uint32_t*)(base + AP + ro + 640);
                al[i][2] = *(const uint32_t*)(base + AP + ro + 16);
                al[i][3] = *(const uint32_t*)(base + AP + ro + 656);
            }
            #pragma unroll
            for (int j = 0; j < 4; j++) {
                int no = 2 * AP + (wn * 32 + j * 8 + r) * 80 + koff;
                bh[j][0] = *(const uint32_t*)(base + no);
                bh[j][1] = *(const uint32_t*)(base + no + 16);
                bl[j][0] = *(const uint32_t*)(base + BP + no);
                bl[j][1] = *(const uint32_t*)(base + BP + no + 16);
            }
            #pragma unroll
            for (int i = 0; i < MF; i++)
                #pragma unroll
                for (int j = 0; j < 4; j++) {
                    mma16816(acc[i][j], ah[i], bh[j]);
                    mma16816(acc[i][j], ah[i], bl[j]);
                    mma16816(acc[i][j], al[i], bh[j]);
                }
        }
        if (s + 1 < KC) {
            #pragma unroll
            for (int u = 0; u < NCH; u++) *sdst(tid + u * 256, buf ^ 1) = rg[u];
        }
        __syncthreads();
    }

    // epilogue
    const int r = lane >> 2, q = lane & 3;
    #pragma unroll
    for (int i = 0; i < MF; i++)
        #pragma unroll
        for (int j = 0; j < 4; j++) {
            int row0 = m0 + wm * WM + i * 16 + r;
            int col = n0 + wn * 32 + j * 8 + q * 2;
            float2* p0 = (float2*)(Cg + ((size_t)t * MGLB + row0) * 1024 + col);
            float2* p1 = (float2*)(Cg + ((size_t)t * MGLB + row0 + 8) * 1024 + col);
            *p0 = make_float2(acc[i][j][0], acc[i][j][1]);
            *p1 = make_float2(acc[i][j][2], acc[i][j][3]);
        }
}

// ---------------- host ----------------
extern "C" void kernel_launch(void* const* d_in, const int* in_sizes, int n_in,
                              void* d_out, int out_size) {
    const float* x     = (const float*)d_in[0];
    const float* ktraj = (const float*)d_in[1];
    const float* csmap = (const float*)d_in[2];
    const float* dcomp = (const float*)d_in[3];
    float* out = (float*)d_out;

    __nv_bfloat16 *pA1, *pA2, *pB1, *pB2;
    float *pC1, *pC2;
    cudaGetSymbolAddress((void**)&pA1, g_A1);
    cudaGetSymbolAddress((void**)&pA2, g_A2);
    cudaGetSymbolAddress((void**)&pB1, g_B1);
    cudaGetSymbolAddress((void**)&pB2, g_B2);
    cudaGetSymbolAddress((void**)&pC1, g_C1);
    cudaGetSymbolAddress((void**)&pC2, g_C2);

    // smem: G1 = 2*(2*128*80 + 2*128*80) = 81920 ; G2 = 2*(2*64*80 + 2*128*80) = 61440
    cudaFuncSetAttribute(k_hmma<128, 256, 4096>, cudaFuncAttributeMaxDynamicSharedMemorySize, 81920);
    cudaFuncSetAttribute(k_hmma<64, 4096, 256>,  cudaFuncAttributeMaxDynamicSharedMemorySize, 61440);

    k_expoA<<<(NTD * NRD * 128 + 255) / 256, 256>>>(ktraj);
    k_expoB<<<(NTD * 128 * NRD + 255) / 256, 256>>>(ktraj);
    k_src  <<<(NTD * 8 * 128 * 128 + 255) / 256, 256>>>(x, csmap);

    // GEMM1: C1[4096 x 1024] = A1[4096 x 256] * B1^T
    {
        dim3 grid(8, 32, NTD);
        k_hmma<128, 256, 4096><<<grid, 256, 81920>>>(pA1, pB1, pC1);
    }
    k_kdat<<<(NTD * 8 * 2048 * 32 + 255) / 256, 256>>>(dcomp);
    k_B2  <<<(NTD * 8 * 128 * 2048 + 255) / 256, 256>>>(0);

    // GEMM2: C2[256 x 1024] = A2[256 x 4096] * B2^T
    {
        dim3 grid(8, 4, NTD);
        k_hmma<64, 4096, 256><<<grid, 256, 61440>>>(pA2, pB2, pC2);
    }
    k_combine<<<(NTD * 128 * 128 + 255) / 256, 256>>>(csmap, out);
}

// round 16
// speedup vs baseline: 1.0012x; 1.0012x over previous
#include <cuda_runtime.h>
#include <cuda_bf16.h>
#include <cstdint>
#include <math.h>

#define NTD 16
#define NRD 2048

// ---------------- scratch (plain row-major, hi/lo bf16 planes) ----------------
__device__ __nv_bfloat16 g_A1[(size_t)16*2*4096*256];   // 64MB  [t][p][m][k]
__device__ __nv_bfloat16 g_B1[(size_t)16*2*1024*256];   // 16MB  [t][p][n][k]
__device__ __nv_bfloat16 g_A2[(size_t)16*2*256*4096];   // 64MB
__device__ __nv_bfloat16 g_B2[(size_t)16*2*1024*4096];  // 256MB
__device__ float  g_C1[(size_t)16*4096*1024];           // 256MB
__device__ float  g_C2[(size_t)16*256*1024];            // 16MB
__device__ float2 g_Ey[(size_t)16*2048*128];            // [t][k][y]
__device__ float2 g_EyT[(size_t)16*128*2048];           // [t][y][k]
__device__ float2 g_g[(size_t)16*8*2048];               // weighted kdat

// write hi/lo split
__device__ __forceinline__ void wr2(__nv_bfloat16* p, size_t ps, float v) {
    __nv_bfloat16 h = __float2bfloat16(v);
    p[0]  = h;
    p[ps] = __float2bfloat16(v - __bfloat162float(h));
}

// ---------------- generators ----------------
__global__ void k_expoA(const float* __restrict__ kt) {
    int idx = blockIdx.x * blockDim.x + threadIdx.x;
    if (idx >= NTD * NRD * 128) return;
    int x = idx & 127, k = (idx >> 7) & 2047, t = idx >> 18;
    float kx = kt[k * NTD + t], ky = kt[(NRD + k) * NTD + t];
    float p = (float)(x - 64);
    float s1, c1, s2, c2;
    sincosf(kx * p, &s1, &c1);
    sincosf(ky * p, &s2, &c2);
    g_Ey[((size_t)t * 2048 + k) * 128 + x] = make_float2(c2, -s2);
    const size_t PS = (size_t)4096 * 256;
    __nv_bfloat16* At = g_A1 + (size_t)t * 2 * PS;
    wr2(At + (size_t)k * 256 + x,              PS,  c1);
    wr2(At + (size_t)k * 256 + 128 + x,        PS,  s1);
    wr2(At + (size_t)(2048 + k) * 256 + x,     PS, -s1);
    wr2(At + (size_t)(2048 + k) * 256 + 128 + x, PS, c1);
}
__global__ void k_expoB(const float* __restrict__ kt) {
    int idx = blockIdx.x * blockDim.x + threadIdx.x;
    if (idx >= NTD * 128 * NRD) return;
    int k = idx & 2047, x = (idx >> 11) & 127, t = idx >> 18;
    float kx = kt[k * NTD + t], ky = kt[(NRD + k) * NTD + t];
    float p = (float)(x - 64);
    float s1, c1, s2, c2;
    sincosf(kx * p, &s1, &c1);
    sincosf(ky * p, &s2, &c2);
    g_EyT[((size_t)t * 128 + x) * 2048 + k] = make_float2(c2, -s2);
    const size_t PS = (size_t)256 * 4096;
    __nv_bfloat16* At = g_A2 + (size_t)t * 2 * PS;
    wr2(At + (size_t)x * 4096 + k,               PS,  c1);
    wr2(At + (size_t)x * 4096 + 2048 + k,        PS, -s1);
    wr2(At + (size_t)(128 + x) * 4096 + k,       PS,  s1);
    wr2(At + (size_t)(128 + x) * 4096 + 2048 + k, PS, c1);
}
__global__ void k_src(const float* __restrict__ xin, const float* __restrict__ csmap) {
    int idx = blockIdx.x * blockDim.x + threadIdx.x;
    if (idx >= NTD * 8 * 128 * 128) return;
    int x = idx & 127, y = (idx >> 7) & 127, c = (idx >> 14) & 7, t = idx >> 17;
    float ir = xin[((0 + x) * 128 + y) * 16 + t];
    float ii = xin[((128 + x) * 128 + y) * 16 + t];
    float sr = csmap[((c * 2 + 0) * 128 + x) * 128 + y];
    float si = csmap[((c * 2 + 1) * 128 + x) * 128 + y];
    float vr = sr * ir - si * ii, vi = sr * ii + si * ir;
    const size_t PS = (size_t)1024 * 256;
    __nv_bfloat16* Bt = g_B1 + (size_t)t * 2 * PS;
    wr2(Bt + (size_t)(c * 128 + y) * 256 + x,       PS, vr);
    wr2(Bt + (size_t)(c * 128 + y) * 256 + 128 + x, PS, vi);
}
// g[c,k] = (sum_y Ey*t1) * d / 16384
__global__ void k_kdat(const float* __restrict__ dcomp) {
    int gt = blockIdx.x * blockDim.x + threadIdx.x;
    int w = gt >> 5, lane = gt & 31;
    if (w >= NTD * 8 * 2048) return;
    int k = w & 2047, c = (w >> 11) & 7, t = w >> 14;
    size_t ro = ((size_t)t * 4096 + k) * 1024 + c * 128;
    size_t io = ((size_t)t * 4096 + 2048 + k) * 1024 + c * 128;
    size_t eo = ((size_t)t * 2048 + k) * 128;
    float ar = 0.f, ai = 0.f;
    #pragma unroll
    for (int i = 0; i < 4; i++) {
        int y = lane + 32 * i;
        float re = g_C1[ro + y], im = g_C1[io + y];
        float2 e = g_Ey[eo + y];
        ar += e.x * re - e.y * im;
        ai += e.x * im + e.y * re;
    }
    #pragma unroll
    for (int o = 16; o; o >>= 1) {
        ar += __shfl_xor_sync(0xffffffffu, ar, o);
        ai += __shfl_xor_sync(0xffffffffu, ai, o);
    }
    if (lane == 0) {
        float d = dcomp[k * NTD + t] * (1.0f / 16384.0f);
        g_g[((size_t)(t * 8 + c)) * 2048 + k] = make_float2(ar * d, ai * d);
    }
}
// B2 = t2 = conj(Ey) * g  (rank-1 regen)
__global__ void k_B2(int) {
    int idx = blockIdx.x * blockDim.x + threadIdx.x;
    if (idx >= NTD * 8 * 128 * 2048) return;
    int k = idx & 2047, y = (idx >> 11) & 127, c = (idx >> 18) & 7, t = idx >> 21;
    float2 e = g_EyT[((size_t)t * 128 + y) * 2048 + k];
    float2 g = g_g[((size_t)(t * 8 + c)) * 2048 + k];
    float tr = e.x * g.x + e.y * g.y;
    float ti = e.x * g.y - e.y * g.x;
    const size_t PS = (size_t)1024 * 4096;
    __nv_bfloat16* Bt = g_B2 + (size_t)t * 2 * PS;
    wr2(Bt + (size_t)(c * 128 + y) * 4096 + k,        PS, tr);
    wr2(Bt + (size_t)(c * 128 + y) * 4096 + 2048 + k, PS, ti);
}
__global__ void k_combine(const float* __restrict__ csmap, float* __restrict__ out) {
    int idx = blockIdx.x * blockDim.x + threadIdx.x;
    if (idx >= NTD * 128 * 128) return;
    int y = idx & 127, x = (idx >> 7) & 127, t = idx >> 14;
    float orr = 0.f, oii = 0.f;
    #pragma unroll
    for (int c = 0; c < 8; c++) {
        float sr = csmap[((c * 2 + 0) * 128 + x) * 128 + y];
        float si = csmap[((c * 2 + 1) * 128 + x) * 128 + y];
        float vr = g_C2[((size_t)t * 256 + x) * 1024 + c * 128 + y];
        float vi = g_C2[((size_t)t * 256 + 128 + x) * 1024 + c * 128 + y];
        orr += sr * vr + si * vi;
        oii += sr * vi - si * vr;
    }
    out[((0 + x) * 128 + y) * 16 + t] = orr;
    out[((128 + x) * 128 + y) * 16 + t] = oii;
}

// ---------------- HMMA GEMM (mma.sync m16n8k16 bf16, 3-product split) ----------------
__device__ __forceinline__ void mma16816(float* d, const uint32_t* a, const uint32_t* b) {
    asm volatile(
        "mma.sync.aligned.m16n8k16.row.col.f32.bf16.bf16.f32 "
        "{%0,%1,%2,%3}, {%4,%5,%6,%7}, {%8,%9}, {%0,%1,%2,%3};"
        : "+f"(d[0]), "+f"(d[1]), "+f"(d[2]), "+f"(d[3])
        : "r"(a[0]), "r"(a[1]), "r"(a[2]), "r"(a[3]), "r"(b[0]), "r"(b[1]));
}

// C[t][MGLB][1024] = A[t][p][MGLB][KGLB] x B[t][p][1024][KGLB]^T with hi/lo split.
// CTA tile CTAM x 128, BK=32, 8 warps (2 x 4), warp tile (CTAM/2) x 32.
template<int CTAM, int KGLB, int MGLB>
__global__ __launch_bounds__(256)
void k_hmma(const __nv_bfloat16* __restrict__ Ag, const __nv_bfloat16* __restrict__ Bg,
            float* __restrict__ Cg) {
    constexpr int WM = CTAM / 2;          // warp m tile
    constexpr int MF = WM / 16;           // m-frags per warp
    constexpr int KC = KGLB / 32;         // k stages
    constexpr int AP = CTAM * 80;         // A plane bytes in smem (padded rows)
    constexpr int BP = 128 * 80;
    constexpr int SB = 2 * AP + 2 * BP;   // per-stage bytes
    constexpr int NA = CTAM * 8;          // A uint4 chunks (2 planes)
    constexpr int NCH = (NA + 1024) / 256;

    extern __shared__ char sm[];
    const int tid = threadIdx.x, lane = tid & 31, wid = tid >> 5;
    const int wm = wid & 1, wn = wid >> 1;
    const int t = blockIdx.z, m0 = blockIdx.y * CTAM, n0 = blockIdx.x * 128;

    float acc[MF][4][4];
    #pragma unroll
    for (int i = 0; i < MF; i++)
        #pragma unroll
        for (int j = 0; j < 4; j++)
            #pragma unroll
            for (int q = 0; q < 4; q++) acc[i][j][q] = 0.f;

    auto gsrc = [&](int i, int k0) -> const uint4* {
        if (i < NA) {
            int p = i / (CTAM * 4), r = (i >> 2) % CTAM, c = i & 3;
            return (const uint4*)(Ag + ((size_t)(t * 2 + p) * MGLB + m0 + r) * KGLB + k0 + c * 8);
        } else {
            int j = i - NA;
            int p = j >> 9, r = (j >> 2) & 127, c = j & 3;
            return (const uint4*)(Bg + ((size_t)(t * 2 + p) * 1024 + n0 + r) * KGLB + k0 + c * 8);
        }
    };
    auto sdst = [&](int i, int buf) -> uint4* {
        if (i < NA) {
            int p = i / (CTAM * 4), r = (i >> 2) % CTAM, c = i & 3;
            return (uint4*)(sm + buf * SB + p * AP + r * 80 + c * 16);
        } else {
            int j = i - NA;
            int p = j >> 9, r = (j >> 2) & 127, c = j & 3;
            return (uint4*)(sm + buf * SB + 2 * AP + p * BP + r * 80 + c * 16);
        }
    };

    // prologue: stage 0
    {
        uint4 rg[NCH];
        #pragma unroll
        for (int u = 0; u < NCH; u++) rg[u] = *gsrc(tid + u * 256, 0);
        #pragma unroll
        for (int u = 0; u < NCH; u++) *sdst(tid + u * 256, 0) = rg[u];
    }
    __syncthreads();

    for (int s = 0; s < KC; s++) {
        const int buf = s & 1;
        uint4 rg[NCH];
        if (s + 1 < KC) {
            #pragma unroll
            for (int u = 0; u < NCH; u++) rg[u] = *gsrc(tid + u * 256, (s + 1) * 32);
        }
        // compute on buf
        const char* base = sm + buf * SB;
        const int r = lane >> 2, q = lane & 3;
        #pragma unroll
        for (int ks = 0; ks < 2; ks++) {
            const int koff = ks * 32 + q * 4;
            uint32_t ah[MF][4], al[MF][4], bh[4][2], bl[4][2];
            #pragma unroll
            for (int i = 0; i < MF; i++) {
                int ro = (wm * WM + i * 16 + r) * 80 + koff;
                ah[i][0] = *(const uint32_t*)(base + ro);
                ah[i][1] = *(const uint32_t*)(base + ro + 640);
                ah[i][2] = *(const uint32_t*)(base + ro + 16);
                ah[i][3] = *(const uint32_t*)(base + ro + 656);
                al[i][0] = *(const uint32_t*)(base + AP + ro);
                al[i][1] = *(const uint32_t*)(base + AP + ro + 640);
                al[i][2] = *(const uint32_t*)(base + AP + ro + 16);
                al[i][3] = *(const uint32_t*)(base + AP + ro + 656);
            }
            #pragma unroll
            for (int j = 0; j < 4; j++) {
                int no = 2 * AP + (wn * 32 + j * 8 + r) * 80 + koff;
                bh[j][0] = *(const uint32_t*)(base + no);
                bh[j][1] = *(const uint32_t*)(base + no + 16);
                bl[j][0] = *(const uint32_t*)(base + BP + no);
                bl[j][1] = *(const uint32_t*)(base + BP + no + 16);
            }
            #pragma unroll
            for (int i = 0; i < MF; i++)
                #pragma unroll
                for (int j = 0; j < 4; j++) {
                    mma16816(acc[i][j], ah[i], bh[j]);
                    mma16816(acc[i][j], ah[i], bl[j]);
                    mma16816(acc[i][j], al[i], bh[j]);
                }
        }
        if (s + 1 < KC) {
            #pragma unroll
            for (int u = 0; u < NCH; u++) *sdst(tid + u * 256, buf ^ 1) = rg[u];
        }
        __syncthreads();
    }

    // epilogue
    const int r = lane >> 2, q = lane & 3;
    #pragma unroll
    for (int i = 0; i < MF; i++)
        #pragma unroll
        for (int j = 0; j < 4; j++) {
            int row0 = m0 + wm * WM + i * 16 + r;
            int col = n0 + wn * 32 + j * 8 + q * 2;
            float2* p0 = (float2*)(Cg + ((size_t)t * MGLB + row0) * 1024 + col);
            float2* p1 = (float2*)(Cg + ((size_t)t * MGLB + row0 + 8) * 1024 + col);
            *p0 = make_float2(acc[i][j][0], acc[i][j][1]);
            *p1 = make_float2(acc[i][j][2], acc[i][j][3]);
        }
}

// ---------------- host ----------------
extern "C" void kernel_launch(void* const* d_in, const int* in_sizes, int n_in,
                              void* d_out, int out_size) {
    const float* x     = (const float*)d_in[0];
    const float* ktraj = (const float*)d_in[1];
    const float* csmap = (const float*)d_in[2];
    const float* dcomp = (const float*)d_in[3];
    float* out = (float*)d_out;

    __nv_bfloat16 *pA1, *pA2, *pB1, *pB2;
    float *pC1, *pC2;
    cudaGetSymbolAddress((void**)&pA1, g_A1);
    cudaGetSymbolAddress((void**)&pA2, g_A2);
    cudaGetSymbolAddress((void**)&pB1, g_B1);
    cudaGetSymbolAddress((void**)&pB2, g_B2);
    cudaGetSymbolAddress((void**)&pC1, g_C1);
    cudaGetSymbolAddress((void**)&pC2, g_C2);

    // smem: G1 = 2*(2*128*80 + 2*128*80) = 81920 ; G2 = 2*(2*64*80 + 2*128*80) = 61440
    cudaFuncSetAttribute(k_hmma<128, 256, 4096>, cudaFuncAttributeMaxDynamicSharedMemorySize, 81920);
    cudaFuncSetAttribute(k_hmma<64, 4096, 256>,  cudaFuncAttributeMaxDynamicSharedMemorySize, 61440);

    k_expoA<<<(NTD * NRD * 128 + 255) / 256, 256>>>(ktraj);
    k_expoB<<<(NTD * 128 * NRD + 255) / 256, 256>>>(ktraj);
    k_src  <<<(NTD * 8 * 128 * 128 + 255) / 256, 256>>>(x, csmap);

    // GEMM1: C1[4096 x 1024] = A1[4096 x 256] * B1^T
    {
        dim3 grid(8, 32, NTD);
        k_hmma<128, 256, 4096><<<grid, 256, 81920>>>(pA1, pB1, pC1);
    }
    k_kdat<<<(NTD * 8 * 2048 * 32 + 255) / 256, 256>>>(dcomp);
    k_B2  <<<(NTD * 8 * 128 * 2048 + 255) / 256, 256>>>(0);

    // GEMM2: C2[256 x 1024] = A2[256 x 4096] * B2^T
    {
        dim3 grid(8, 4, NTD);
        k_hmma<64, 4096, 256><<<grid, 256, 61440>>>(pA2, pB2, pC2);
    }
    k_combine<<<(NTD * 128 * 128 + 255) / 256, 256>>>(csmap, out);
}

// round 17
// speedup vs baseline: 1.0013x; 1.0002x over previous
#include <cuda_runtime.h>
#include <cuda_bf16.h>
#include <cstdint>
#include <math.h>

#define NTD 16
#define NRD 2048

// ---------------- scratch (plain row-major, hi/lo bf16 planes) ----------------
__device__ __nv_bfloat16 g_A1[(size_t)16*2*4096*256];   // 64MB  [t][p][m][k]
__device__ __nv_bfloat16 g_B1[(size_t)16*2*1024*256];   // 16MB  [t][p][n][k]
__device__ __nv_bfloat16 g_A2[(size_t)16*2*256*4096];   // 64MB
__device__ __nv_bfloat16 g_B2[(size_t)16*2*1024*4096];  // 256MB
__device__ float  g_C1[(size_t)16*4096*1024];           // 256MB
__device__ float  g_C2[(size_t)16*256*1024];            // 16MB
__device__ float2 g_Ey[(size_t)16*2048*128];            // [t][k][y]
__device__ float2 g_EyT[(size_t)16*128*2048];           // [t][y][k]
__device__ float2 g_g[(size_t)16*8*2048];               // weighted kdat

// write hi/lo split
__device__ __forceinline__ void wr2(__nv_bfloat16* p, size_t ps, float v) {
    __nv_bfloat16 h = __float2bfloat16(v);
    p[0]  = h;
    p[ps] = __float2bfloat16(v - __bfloat162float(h));
}

// ---------------- generators ----------------
__global__ void k_expoA(const float* __restrict__ kt) {
    int idx = blockIdx.x * blockDim.x + threadIdx.x;
    if (idx >= NTD * NRD * 128) return;
    int x = idx & 127, k = (idx >> 7) & 2047, t = idx >> 18;
    float kx = kt[k * NTD + t], ky = kt[(NRD + k) * NTD + t];
    float p = (float)(x - 64);
    float s1, c1, s2, c2;
    sincosf(kx * p, &s1, &c1);
    sincosf(ky * p, &s2, &c2);
    g_Ey[((size_t)t * 2048 + k) * 128 + x] = make_float2(c2, -s2);
    const size_t PS = (size_t)4096 * 256;
    __nv_bfloat16* At = g_A1 + (size_t)t * 2 * PS;
    wr2(At + (size_t)k * 256 + x,              PS,  c1);
    wr2(At + (size_t)k * 256 + 128 + x,        PS,  s1);
    wr2(At + (size_t)(2048 + k) * 256 + x,     PS, -s1);
    wr2(At + (size_t)(2048 + k) * 256 + 128 + x, PS, c1);
}
__global__ void k_expoB(const float* __restrict__ kt) {
    int idx = blockIdx.x * blockDim.x + threadIdx.x;
    if (idx >= NTD * 128 * NRD) return;
    int k = idx & 2047, x = (idx >> 11) & 127, t = idx >> 18;
    float kx = kt[k * NTD + t], ky = kt[(NRD + k) * NTD + t];
    float p = (float)(x - 64);
    float s1, c1, s2, c2;
    sincosf(kx * p, &s1, &c1);
    sincosf(ky * p, &s2, &c2);
    g_EyT[((size_t)t * 128 + x) * 2048 + k] = make_float2(c2, -s2);
    const size_t PS = (size_t)256 * 4096;
    __nv_bfloat16* At = g_A2 + (size_t)t * 2 * PS;
    wr2(At + (size_t)x * 4096 + k,               PS,  c1);
    wr2(At + (size_t)x * 4096 + 2048 + k,        PS, -s1);
    wr2(At + (size_t)(128 + x) * 4096 + k,       PS,  s1);
    wr2(At + (size_t)(128 + x) * 4096 + 2048 + k, PS, c1);
}
__global__ void k_src(const float* __restrict__ xin, const float* __restrict__ csmap) {
    int idx = blockIdx.x * blockDim.x + threadIdx.x;
    if (idx >= NTD * 8 * 128 * 128) return;
    int x = idx & 127, y = (idx >> 7) & 127, c = (idx >> 14) & 7, t = idx >> 17;
    float ir = xin[((0 + x) * 128 + y) * 16 + t];
    float ii = xin[((128 + x) * 128 + y) * 16 + t];
    float sr = csmap[((c * 2 + 0) * 128 + x) * 128 + y];
    float si = csmap[((c * 2 + 1) * 128 + x) * 128 + y];
    float vr = sr * ir - si * ii, vi = sr * ii + si * ir;
    const size_t PS = (size_t)1024 * 256;
    __nv_bfloat16* Bt = g_B1 + (size_t)t * 2 * PS;
    wr2(Bt + (size_t)(c * 128 + y) * 256 + x,       PS, vr);
    wr2(Bt + (size_t)(c * 128 + y) * 256 + 128 + x, PS, vi);
}
// g[c,k] = (sum_y Ey*t1) * d / 16384
__global__ void k_kdat(const float* __restrict__ dcomp) {
    int gt = blockIdx.x * blockDim.x + threadIdx.x;
    int w = gt >> 5, lane = gt & 31;
    if (w >= NTD * 8 * 2048) return;
    int k = w & 2047, c = (w >> 11) & 7, t = w >> 14;
    size_t ro = ((size_t)t * 4096 + k) * 1024 + c * 128;
    size_t io = ((size_t)t * 4096 + 2048 + k) * 1024 + c * 128;
    size_t eo = ((size_t)t * 2048 + k) * 128;
    float ar = 0.f, ai = 0.f;
    #pragma unroll
    for (int i = 0; i < 4; i++) {
        int y = lane + 32 * i;
        float re = g_C1[ro + y], im = g_C1[io + y];
        float2 e = g_Ey[eo + y];
        ar += e.x * re - e.y * im;
        ai += e.x * im + e.y * re;
    }
    #pragma unroll
    for (int o = 16; o; o >>= 1) {
        ar += __shfl_xor_sync(0xffffffffu, ar, o);
        ai += __shfl_xor_sync(0xffffffffu, ai, o);
    }
    if (lane == 0) {
        float d = dcomp[k * NTD + t] * (1.0f / 16384.0f);
        g_g[((size_t)(t * 8 + c)) * 2048 + k] = make_float2(ar * d, ai * d);
    }
}
// B2 = t2 = conj(Ey) * g  (rank-1 regen)
__global__ void k_B2(int) {
    int idx = blockIdx.x * blockDim.x + threadIdx.x;
    if (idx >= NTD * 8 * 128 * 2048) return;
    int k = idx & 2047, y = (idx >> 11) & 127, c = (idx >> 18) & 7, t = idx >> 21;
    float2 e = g_EyT[((size_t)t * 128 + y) * 2048 + k];
    float2 g = g_g[((size_t)(t * 8 + c)) * 2048 + k];
    float tr = e.x * g.x + e.y * g.y;
    float ti = e.x * g.y - e.y * g.x;
    const size_t PS = (size_t)1024 * 4096;
    __nv_bfloat16* Bt = g_B2 + (size_t)t * 2 * PS;
    wr2(Bt + (size_t)(c * 128 + y) * 4096 + k,        PS, tr);
    wr2(Bt + (size_t)(c * 128 + y) * 4096 + 2048 + k, PS, ti);
}
__global__ void k_combine(const float* __restrict__ csmap, float* __restrict__ out) {
    int idx = blockIdx.x * blockDim.x + threadIdx.x;
    if (idx >= NTD * 128 * 128) return;
    int y = idx & 127, x = (idx >> 7) & 127, t = idx >> 14;
    float orr = 0.f, oii = 0.f;
    #pragma unroll
    for (int c = 0; c < 8; c++) {
        float sr = csmap[((c * 2 + 0) * 128 + x) * 128 + y];
        float si = csmap[((c * 2 + 1) * 128 + x) * 128 + y];
        float vr = g_C2[((size_t)t * 256 + x) * 1024 + c * 128 + y];
        float vi = g_C2[((size_t)t * 256 + 128 + x) * 1024 + c * 128 + y];
        orr += sr * vr + si * vi;
        oii += sr * vi - si * vr;
    }
    out[((0 + x) * 128 + y) * 16 + t] = orr;
    out[((128 + x) * 128 + y) * 16 + t] = oii;
}

// ---------------- HMMA GEMM (mma.sync m16n8k16 bf16, 3-product split) ----------------
__device__ __forceinline__ void mma16816(float* d, const uint32_t* a, const uint32_t* b) {
    asm volatile(
        "mma.sync.aligned.m16n8k16.row.col.f32.bf16.bf16.f32 "
        "{%0,%1,%2,%3}, {%4,%5,%6,%7}, {%8,%9}, {%0,%1,%2,%3};"
        : "+f"(d[0]), "+f"(d[1]), "+f"(d[2]), "+f"(d[3])
        : "r"(a[0]), "r"(a[1]), "r"(a[2]), "r"(a[3]), "r"(b[0]), "r"(b[1]));
}

// C[t][MGLB][1024] = A[t][p][MGLB][KGLB] x B[t][p][1024][KGLB]^T with hi/lo split.
// CTA tile CTAM x 128, BK=32, 8 warps (2 x 4), warp tile (CTAM/2) x 32.
template<int CTAM, int KGLB, int MGLB>
__global__ __launch_bounds__(256)
void k_hmma(const __nv_bfloat16* __restrict__ Ag, const __nv_bfloat16* __restrict__ Bg,
            float* __restrict__ Cg) {
    constexpr int WM = CTAM / 2;          // warp m tile
    constexpr int MF = WM / 16;           // m-frags per warp
    constexpr int KC = KGLB / 32;         // k stages
    constexpr int AP = CTAM * 80;         // A plane bytes in smem (padded rows)
    constexpr int BP = 128 * 80;
    constexpr int SB = 2 * AP + 2 * BP;   // per-stage bytes
    constexpr int NA = CTAM * 8;          // A uint4 chunks (2 planes)
    constexpr int NCH = (NA + 1024) / 256;

    extern __shared__ char sm[];
    const int tid = threadIdx.x, lane = tid & 31, wid = tid >> 5;
    const int wm = wid & 1, wn = wid >> 1;
    const int t = blockIdx.z, m0 = blockIdx.y * CTAM, n0 = blockIdx.x * 128;

    float acc[MF][4][4];
    #pragma unroll
    for (int i = 0; i < MF; i++)
        #pragma unroll
        for (int j = 0; j < 4; j++)
            #pragma unroll
            for (int q = 0; q < 4; q++) acc[i][j][q] = 0.f;

    auto gsrc = [&](int i, int k0) -> const uint4* {
        if (i < NA) {
            int p = i / (CTAM * 4), r = (i >> 2) % CTAM, c = i & 3;
            return (const uint4*)(Ag + ((size_t)(t * 2 + p) * MGLB + m0 + r) * KGLB + k0 + c * 8);
        } else {
            int j = i - NA;
            int p = j >> 9, r = (j >> 2) & 127, c = j & 3;
            return (const uint4*)(Bg + ((size_t)(t * 2 + p) * 1024 + n0 + r) * KGLB + k0 + c * 8);
        }
    };
    auto sdst = [&](int i, int buf) -> uint4* {
        if (i < NA) {
            int p = i / (CTAM * 4), r = (i >> 2) % CTAM, c = i & 3;
            return (uint4*)(sm + buf * SB + p * AP + r * 80 + c * 16);
        } else {
            int j = i - NA;
            int p = j >> 9, r = (j >> 2) & 127, c = j & 3;
            return (uint4*)(sm + buf * SB + 2 * AP + p * BP + r * 80 + c * 16);
        }
    };

    // prologue: stage 0
    {
        uint4 rg[NCH];
        #pragma unroll
        for (int u = 0; u < NCH; u++) rg[u] = *gsrc(tid + u * 256, 0);
        #pragma unroll
        for (int u = 0; u < NCH; u++) *sdst(tid + u * 256, 0) = rg[u];
    }
    __syncthreads();

    for (int s = 0; s < KC; s++) {
        const int buf = s & 1;
        uint4 rg[NCH];
        if (s + 1 < KC) {
            #pragma unroll
            for (int u = 0; u < NCH; u++) rg[u] = *gsrc(tid + u * 256, (s + 1) * 32);
        }
        // compute on buf
        const char* base = sm + buf * SB;
        const int r = lane >> 2, q = lane & 3;
        #pragma unroll
        for (int ks = 0; ks < 2; ks++) {
            const int koff = ks * 32 + q * 4;
            uint32_t ah[MF][4], al[MF][4], bh[4][2], bl[4][2];
            #pragma unroll
            for (int i = 0; i < MF; i++) {
                int ro = (wm * WM + i * 16 + r) * 80 + koff;
                ah[i][0] = *(const uint32_t*)(base + ro);
                ah[i][1] = *(const uint32_t*)(base + ro + 640);
                ah[i][2] = *(const uint32_t*)(base + ro + 16);
                ah[i][3] = *(const uint32_t*)(base + ro + 656);
                al[i][0] = *(const uint32_t*)(base + AP + ro);
                al[i][1] = *(const uint32_t*)(base + AP + ro + 640);
                al[i][2] = *(const uint32_t*)(base + AP + ro + 16);
                al[i][3] = *(const uint32_t*)(base + AP + ro + 656);
            }
            #pragma unroll
            for (int j = 0; j < 4; j++) {
                int no = 2 * AP + (wn * 32 + j * 8 + r) * 80 + koff;
                bh[j][0] = *(const uint32_t*)(base + no);
                bh[j][1] = *(const uint32_t*)(base + no + 16);
                bl[j][0] = *(const uint32_t*)(base + BP + no);
                bl[j][1] = *(const uint32_t*)(base + BP + no + 16);
            }
            #pragma unroll
            for (int i = 0; i < MF; i++)
                #pragma unroll
                for (int j = 0; j < 4; j++) {
                    mma16816(acc[i][j], ah[i], bh[j]);
                    mma16816(acc[i][j], ah[i], bl[j]);
                    mma16816(acc[i][j], al[i], bh[j]);
                }
        }
        if (s + 1 < KC) {
            #pragma unroll
            for (int u = 0; u < NCH; u++) *sdst(tid + u * 256, buf ^ 1) = rg[u];
        }
        __syncthreads();
    }

    // epilogue
    const int r = lane >> 2, q = lane & 3;
    #pragma unroll
    for (int i = 0; i < MF; i++)
        #pragma unroll
        for (int j = 0; j < 4; j++) {
            int row0 = m0 + wm * WM + i * 16 + r;
            int col = n0 + wn * 32 + j * 8 + q * 2;
            float2* p0 = (float2*)(Cg + ((size_t)t * MGLB + row0) * 1024 + col);
            float2* p1 = (float2*)(Cg + ((size_t)t * MGLB + row0 + 8) * 1024 + col);
            *p0 = make_float2(acc[i][j][0], acc[i][j][1]);
            *p1 = make_float2(acc[i][j][2], acc[i][j][3]);
        }
}

// ---------------- host ----------------
extern "C" void kernel_launch(void* const* d_in, const int* in_sizes, int n_in,
                              void* d_out, int out_size) {
    const float* x     = (const float*)d_in[0];
    const float* ktraj = (const float*)d_in[1];
    const float* csmap = (const float*)d_in[2];
    const float* dcomp = (const float*)d_in[3];
    float* out = (float*)d_out;

    __nv_bfloat16 *pA1, *pA2, *pB1, *pB2;
    float *pC1, *pC2;
    cudaGetSymbolAddress((void**)&pA1, g_A1);
    cudaGetSymbolAddress((void**)&pA2, g_A2);
    cudaGetSymbolAddress((void**)&pB1, g_B1);
    cudaGetSymbolAddress((void**)&pB2, g_B2);
    cudaGetSymbolAddress((void**)&pC1, g_C1);
    cudaGetSymbolAddress((void**)&pC2, g_C2);

    // smem: G1 = 2*(2*128*80 + 2*128*80) = 81920 ; G2 = 2*(2*64*80 + 2*128*80) = 61440
    cudaFuncSetAttribute(k_hmma<128, 256, 4096>, cudaFuncAttributeMaxDynamicSharedMemorySize, 81920);
    cudaFuncSetAttribute(k_hmma<64, 4096, 256>,  cudaFuncAttributeMaxDynamicSharedMemorySize, 61440);

    k_expoA<<<(NTD * NRD * 128 + 255) / 256, 256>>>(ktraj);
    k_expoB<<<(NTD * 128 * NRD + 255) / 256, 256>>>(ktraj);
    k_src  <<<(NTD * 8 * 128 * 128 + 255) / 256, 256>>>(x, csmap);

    // GEMM1: C1[4096 x 1024] = A1[4096 x 256] * B1^T
    {
        dim3 grid(8, 32, NTD);
        k_hmma<128, 256, 4096><<<grid, 256, 81920>>>(pA1, pB1, pC1);
    }
    k_kdat<<<(NTD * 8 * 2048 * 32 + 255) / 256, 256>>>(dcomp);
    k_B2  <<<(NTD * 8 * 128 * 2048 + 255) / 256, 256>>>(0);

    // GEMM2: C2[256 x 1024] = A2[256 x 4096] * B2^T
    {
        dim3 grid(8, 4, NTD);
        k_hmma<64, 4096, 256><<<grid, 256, 61440>>>(pA2, pB2, pC2);
    }
    k_combine<<<(NTD * 128 * 128 + 255) / 256, 256>>>(csmap, out);
}